// round 1
// baseline (speedup 1.0000x reference)
#include <cuda_runtime.h>
#include <cuda_bf16.h>
#include <math.h>

// Problem constants
#define NB   16
#define CIN  128
#define COUT 128
#define KK   3
#define HH   64
#define WW   64
#define HO   64
#define WO   64
#define PP   9      // K*K
#define HW   (HH*WW)        // 4096
#define PIX_PER_N (HO*WO)   // 4096

// ---------------- scratch (allocation-free: __device__ globals) ----------------
__device__ float  g_xT[NB * HH * WW * CIN];         // NHWC transpose of x (33.5 MB)
__device__ float4 g_meta[NB * PP * HO * WO];        // per (n,p,pixel): y0,x0 (bitcast int), wy, wx
__device__ float  g_wT[PP * CIN * COUT];            // deform_w transposed to [p][cin][cout]

// ---------------- kernel 1: x NCHW -> NHWC ----------------
__global__ void k_transpose_x(const float* __restrict__ x) {
    __shared__ float tile[32][33];
    int n   = blockIdx.z;
    int hw0 = blockIdx.x * 32;
    int c0  = blockIdx.y * 32;
    int tx = threadIdx.x, ty = threadIdx.y;
    #pragma unroll
    for (int i = 0; i < 32; i += 8)
        tile[ty + i][tx] = x[((size_t)(n * CIN + c0 + ty + i)) * HW + hw0 + tx];
    __syncthreads();
    #pragma unroll
    for (int i = 0; i < 32; i += 8)
        g_xT[((size_t)(n * HW + hw0 + ty + i)) * CIN + c0 + tx] = tile[tx][ty + i];
}

// ---------------- kernel 2: deform_w [cout][cin][p] -> wT [p][cin][cout] ----------------
__global__ void k_transpose_w(const float* __restrict__ w) {
    int i = blockIdx.x * blockDim.x + threadIdx.x;   // output-linear index
    if (i >= PP * CIN * COUT) return;
    int cout = i & 127;
    int cin  = (i >> 7) & 127;
    int p    = i >> 14;
    g_wT[i] = w[(cout * CIN + cin) * PP + p];
}

// ---------------- kernel 3: offset conv + bilinear metadata ----------------
// warp handles 4 consecutive wo pixels; lane covers cin (4 chunks of 32).
// smem: weights padded [p][cin][19] + per-warp staging of reduced sums.
__global__ void k_offset_meta(const float* __restrict__ offset_w,
                              const float* __restrict__ offset_b) {
    extern __shared__ float sm[];
    float* wsh = sm;                       // 9*128*19 = 21888 floats
    float* ash = sm + PP * CIN * 19;       // 8 warps * 72 floats

    int tid = threadIdx.x;
    // load offset weights into smem: wsh[(p*128+cin)*19 + ch]
    for (int i = tid; i < 18 * CIN * PP; i += blockDim.x) {
        int ch   = i % 18;
        int rest = i / 18;
        int cin  = rest & 127;
        int p    = rest >> 7;
        wsh[(p * CIN + cin) * 19 + ch] = offset_w[(ch * CIN + cin) * PP + p];
    }
    __syncthreads();

    int lane = tid & 31;
    int warp = tid >> 5;
    int gw   = blockIdx.x * 8 + warp;          // global warp id
    int pb   = gw * 4;                          // pixel base (4 consecutive wo)
    int n    = pb >> 12;
    int r    = pb & 4095;
    int ho   = r >> 6;
    int wo0  = r & 63;

    float acc[4][18];
    #pragma unroll
    for (int j = 0; j < 4; j++)
        #pragma unroll
        for (int ch = 0; ch < 18; ch++) acc[j][ch] = 0.f;

    const float* xn = g_xT + (size_t)n * HW * CIN;

    #pragma unroll
    for (int p = 0; p < PP; p++) {
        int ky = p / 3, kx = p % 3;
        int ih = ho + ky - 1;
        bool vrow = (unsigned)ih < (unsigned)HH;
        #pragma unroll
        for (int cc = 0; cc < 4; cc++) {
            int cin = cc * 32 + lane;
            float xv[4];
            #pragma unroll
            for (int j = 0; j < 4; j++) {
                int iw = wo0 + j + kx - 1;
                bool v = vrow && ((unsigned)iw < (unsigned)WW);
                xv[j] = v ? xn[((size_t)(ih * WW + iw)) * CIN + cin] : 0.f;
            }
            const float* wrow = &wsh[(p * CIN + cin) * 19];
            #pragma unroll
            for (int ch = 0; ch < 18; ch++) {
                float w = wrow[ch];
                acc[0][ch] += xv[0] * w;
                acc[1][ch] += xv[1] * w;
                acc[2][ch] += xv[2] * w;
                acc[3][ch] += xv[3] * w;
            }
        }
    }

    // reduce over lanes (cin) — shfl-down tree, result on lane 0
    #pragma unroll
    for (int off = 16; off > 0; off >>= 1)
        #pragma unroll
        for (int j = 0; j < 4; j++)
            #pragma unroll
            for (int ch = 0; ch < 18; ch++)
                acc[j][ch] += __shfl_down_sync(0xffffffffu, acc[j][ch], off);

    float* aw = ash + warp * 72;
    if (lane == 0) {
        #pragma unroll
        for (int j = 0; j < 4; j++)
            #pragma unroll
            for (int ch = 0; ch < 18; ch++)
                aw[j * 18 + ch] = acc[j][ch];
    }
    __syncwarp();

    // 36 items = 4 pixels x 9 taps
    for (int item = lane; item < 36; item += 32) {
        int j = item / 9;
        int p = item % 9;
        int ky = p / 3, kx = p % 3;
        float dy = aw[j * 18 + 2 * p]     + offset_b[2 * p];
        float dx = aw[j * 18 + 2 * p + 1] + offset_b[2 * p + 1];
        float py = dy + (float)ky + (float)(ho - 1);
        float px = dx + (float)kx + (float)(wo0 + j - 1);
        float y0f = floorf(py);
        float x0f = floorf(px);
        float wy = py - y0f;
        float wx = px - x0f;
        int y0 = (int)y0f;
        int x0 = (int)x0f;
        g_meta[((size_t)(n * PP + p)) * PIX_PER_N + ho * WO + wo0 + j] =
            make_float4(__int_as_float(y0), __int_as_float(x0), wy, wx);
    }
}

// ---------------- kernel 4: fused gather + GEMM + BN + SiLU ----------------
// block = one (n, ho) row: 64 pixels x 128 couts, K = 9*128.
// smem: Bs[128][128] | As[64][132] | msh[9][64] float4 | ssh[128] | bsh[128]
#define AS_STRIDE 132
__global__ void k_main(const float* __restrict__ gamma,
                       const float* __restrict__ beta,
                       const float* __restrict__ rmean,
                       const float* __restrict__ rvar,
                       float* __restrict__ out) {
    extern __shared__ float sm[];
    float*  Bs  = sm;                                  // 16384 floats
    float*  As  = sm + 16384;                          // 64*132 = 8448 floats
    float4* msh = (float4*)(sm + 16384 + 8448);        // 576 float4
    float*  ssh = sm + 16384 + 8448 + 2304;            // 128
    float*  bsh = ssh + 128;                           // 128

    int tid = threadIdx.x;
    int ho  = blockIdx.x;
    int n   = blockIdx.y;

    // stage all tap metadata for this row + BN scale/bias
    for (int i = tid; i < PP * 64; i += 256) {
        int p  = i >> 6;
        int wo = i & 63;
        msh[i] = g_meta[((size_t)(n * PP + p)) * PIX_PER_N + ho * WO + wo];
    }
    if (tid < COUT) {
        float s = gamma[tid] * rsqrtf(rvar[tid] + 1e-5f);
        ssh[tid] = s;
        bsh[tid] = beta[tid] - rmean[tid] * s;
    }
    __syncthreads();

    int lane = tid & 31;
    int warp = tid >> 5;
    int pr    = tid >> 4;        // 0..15 pixel group
    int cr    = tid & 15;        // 0..15 cout group
    int pix0  = pr * 4;
    int cout0 = cr * 8;

    float acc[4][8];
    #pragma unroll
    for (int j = 0; j < 4; j++)
        #pragma unroll
        for (int c = 0; c < 8; c++) acc[j][c] = 0.f;

    const float* xn = g_xT + (size_t)n * HW * CIN;

    for (int p = 0; p < PP; p++) {
        // ---- gather As[pix][cin]: warp handles 8 pixels, lanes over cin ----
        int gpix0 = warp * 8;
        #pragma unroll
        for (int pl = 0; pl < 8; pl++) {
            int pix = gpix0 + pl;
            float4 m = msh[p * 64 + pix];
            int y0 = __float_as_int(m.x);
            int x0 = __float_as_int(m.y);
            float wy = m.z, wx = m.w;
            float w00 = (1.f - wy) * (1.f - wx);
            float w01 = (1.f - wy) * wx;
            float w10 = wy * (1.f - wx);
            float w11 = wy * wx;
            bool vy0 = (unsigned)y0       < (unsigned)HH;
            bool vy1 = (unsigned)(y0 + 1) < (unsigned)HH;
            bool vx0 = (unsigned)x0       < (unsigned)WW;
            bool vx1 = (unsigned)(x0 + 1) < (unsigned)WW;
            const float* r0 = xn + ((size_t)(y0 * WW)) * CIN;
            const float* r1 = r0 + (size_t)WW * CIN;
            #pragma unroll
            for (int cc = 0; cc < 4; cc++) {
                int c = cc * 32 + lane;
                float v = 0.f;
                if (vy0) {
                    if (vx0) v += w00 * r0[x0 * CIN + c];
                    if (vx1) v += w01 * r0[(x0 + 1) * CIN + c];
                }
                if (vy1) {
                    if (vx0) v += w10 * r1[x0 * CIN + c];
                    if (vx1) v += w11 * r1[(x0 + 1) * CIN + c];
                }
                As[pix * AS_STRIDE + c] = v;
            }
        }
        // ---- load Bs[k][cout] for this tap ----
        {
            const float4* src = (const float4*)(g_wT + (size_t)p * CIN * COUT);
            float4* dst = (float4*)Bs;
            #pragma unroll
            for (int i = tid; i < CIN * COUT / 4; i += 256)
                dst[i] = src[i];
        }
        __syncthreads();

        // ---- GEMM: 64x128 += As(64x128) * Bs(128x128) ----
        #pragma unroll 8
        for (int k = 0; k < CIN; k++) {
            float a0 = As[(pix0 + 0) * AS_STRIDE + k];
            float a1 = As[(pix0 + 1) * AS_STRIDE + k];
            float a2 = As[(pix0 + 2) * AS_STRIDE + k];
            float a3 = As[(pix0 + 3) * AS_STRIDE + k];
            float4 b0 = *(const float4*)&Bs[k * COUT + cout0];
            float4 b1 = *(const float4*)&Bs[k * COUT + cout0 + 4];
            acc[0][0] += a0 * b0.x; acc[0][1] += a0 * b0.y; acc[0][2] += a0 * b0.z; acc[0][3] += a0 * b0.w;
            acc[0][4] += a0 * b1.x; acc[0][5] += a0 * b1.y; acc[0][6] += a0 * b1.z; acc[0][7] += a0 * b1.w;
            acc[1][0] += a1 * b0.x; acc[1][1] += a1 * b0.y; acc[1][2] += a1 * b0.z; acc[1][3] += a1 * b0.w;
            acc[1][4] += a1 * b1.x; acc[1][5] += a1 * b1.y; acc[1][6] += a1 * b1.z; acc[1][7] += a1 * b1.w;
            acc[2][0] += a2 * b0.x; acc[2][1] += a2 * b0.y; acc[2][2] += a2 * b0.z; acc[2][3] += a2 * b0.w;
            acc[2][4] += a2 * b1.x; acc[2][5] += a2 * b1.y; acc[2][6] += a2 * b1.z; acc[2][7] += a2 * b1.w;
            acc[3][0] += a3 * b0.x; acc[3][1] += a3 * b0.y; acc[3][2] += a3 * b0.z; acc[3][3] += a3 * b0.w;
            acc[3][4] += a3 * b1.x; acc[3][5] += a3 * b1.y; acc[3][6] += a3 * b1.z; acc[3][7] += a3 * b1.w;
        }
        __syncthreads();
    }

    // ---- epilogue: BN + SiLU, vectorized store (4 consecutive wo) ----
    #pragma unroll
    for (int c = 0; c < 8; c++) {
        int co = cout0 + c;
        float s = ssh[co], b = bsh[co];
        float4 v;
        float y;
        y = acc[0][c] * s + b; v.x = y / (1.f + expf(-y));
        y = acc[1][c] * s + b; v.y = y / (1.f + expf(-y));
        y = acc[2][c] * s + b; v.z = y / (1.f + expf(-y));
        y = acc[3][c] * s + b; v.w = y / (1.f + expf(-y));
        *(float4*)&out[(((size_t)(n * COUT + co)) * HO + ho) * WO + pix0] = v;
    }
}

// ---------------- launch ----------------
extern "C" void kernel_launch(void* const* d_in, const int* in_sizes, int n_in,
                              void* d_out, int out_size) {
    const float* x        = (const float*)d_in[0];
    const float* offset_w = (const float*)d_in[1];
    const float* offset_b = (const float*)d_in[2];
    const float* deform_w = (const float*)d_in[3];
    const float* gamma    = (const float*)d_in[4];
    const float* beta     = (const float*)d_in[5];
    const float* rmean    = (const float*)d_in[6];
    const float* rvar     = (const float*)d_in[7];
    float* out = (float*)d_out;

    static bool attr_done = false;
    if (!attr_done) {
        cudaFuncSetAttribute(k_offset_meta, cudaFuncAttributeMaxDynamicSharedMemorySize, 90000);
        cudaFuncSetAttribute(k_main,        cudaFuncAttributeMaxDynamicSharedMemorySize, 110592);
        attr_done = true;
    }

    k_transpose_x<<<dim3(HW / 32, CIN / 32, NB), dim3(32, 8)>>>(x);
    k_transpose_w<<<(PP * CIN * COUT + 255) / 256, 256>>>(deform_w);

    size_t sm3 = (size_t)(PP * CIN * 19 + 8 * 72) * sizeof(float);   // 89856 B
    k_offset_meta<<<NB * PIX_PER_N / 32, 256, sm3>>>(offset_w, offset_b);

    size_t sm4 = (size_t)(16384 + 8448 + 2304 + 256) * sizeof(float); // 109568 B
    k_main<<<dim3(HO, NB), 256, sm4>>>(gamma, beta, rmean, rvar, out);
}

// round 2
// speedup vs baseline: 1.4065x; 1.4065x over previous
#include <cuda_runtime.h>
#include <cuda_bf16.h>
#include <math.h>

typedef unsigned long long ull;

// Problem constants
#define NB   16
#define CIN  128
#define COUT 128
#define KK   3
#define HH   64
#define WW   64
#define HO   64
#define WO   64
#define PP   9      // K*K
#define HW   (HH*WW)        // 4096
#define PIX_PER_N (HO*WO)   // 4096

// ---------------- scratch (allocation-free: __device__ globals) ----------------
__device__ float  g_xT[NB * HH * WW * CIN];         // NHWC transpose of x (33.5 MB)
__device__ float4 g_meta[NB * PP * HO * WO];        // per (n,p,pixel): y0,x0 (bitcast int), wy, wx
__device__ float  g_wT[PP * CIN * COUT];            // deform_w transposed to [p][cin][cout]

// ---------------- kernel 1: x NCHW -> NHWC ----------------
__global__ void k_transpose_x(const float* __restrict__ x) {
    __shared__ float tile[32][33];
    int n   = blockIdx.z;
    int hw0 = blockIdx.x * 32;
    int c0  = blockIdx.y * 32;
    int tx = threadIdx.x, ty = threadIdx.y;
    #pragma unroll
    for (int i = 0; i < 32; i += 8)
        tile[ty + i][tx] = x[((size_t)(n * CIN + c0 + ty + i)) * HW + hw0 + tx];
    __syncthreads();
    #pragma unroll
    for (int i = 0; i < 32; i += 8)
        g_xT[((size_t)(n * HW + hw0 + ty + i)) * CIN + c0 + tx] = tile[tx][ty + i];
}

// ---------------- kernel 2: deform_w [cout][cin][p] -> wT [p][cin][cout] ----------------
__global__ void k_transpose_w(const float* __restrict__ w) {
    int i = blockIdx.x * blockDim.x + threadIdx.x;   // output-linear index
    if (i >= PP * CIN * COUT) return;
    int cout = i & 127;
    int cin  = (i >> 7) & 127;
    int p    = i >> 14;
    g_wT[i] = w[(cout * CIN + cin) * PP + p];
}

// ---------------- kernel 3: offset conv + bilinear metadata ----------------
__global__ void k_offset_meta(const float* __restrict__ offset_w,
                              const float* __restrict__ offset_b) {
    extern __shared__ float sm[];
    float* wsh = sm;                       // 9*128*19 = 21888 floats
    float* ash = sm + PP * CIN * 19;       // 8 warps * 72 floats

    int tid = threadIdx.x;
    for (int i = tid; i < 18 * CIN * PP; i += blockDim.x) {
        int ch   = i % 18;
        int rest = i / 18;
        int cin  = rest & 127;
        int p    = rest >> 7;
        wsh[(p * CIN + cin) * 19 + ch] = offset_w[(ch * CIN + cin) * PP + p];
    }
    __syncthreads();

    int lane = tid & 31;
    int warp = tid >> 5;
    int gw   = blockIdx.x * 8 + warp;          // global warp id
    int pb   = gw * 4;                          // pixel base (4 consecutive wo)
    int n    = pb >> 12;
    int r    = pb & 4095;
    int ho   = r >> 6;
    int wo0  = r & 63;

    float acc[4][18];
    #pragma unroll
    for (int j = 0; j < 4; j++)
        #pragma unroll
        for (int ch = 0; ch < 18; ch++) acc[j][ch] = 0.f;

    const float* xn = g_xT + (size_t)n * HW * CIN;

    #pragma unroll
    for (int p = 0; p < PP; p++) {
        int ky = p / 3, kx = p % 3;
        int ih = ho + ky - 1;
        bool vrow = (unsigned)ih < (unsigned)HH;
        #pragma unroll
        for (int cc = 0; cc < 4; cc++) {
            int cin = cc * 32 + lane;
            float xv[4];
            #pragma unroll
            for (int j = 0; j < 4; j++) {
                int iw = wo0 + j + kx - 1;
                bool v = vrow && ((unsigned)iw < (unsigned)WW);
                xv[j] = v ? xn[((size_t)(ih * WW + iw)) * CIN + cin] : 0.f;
            }
            const float* wrow = &wsh[(p * CIN + cin) * 19];
            #pragma unroll
            for (int ch = 0; ch < 18; ch++) {
                float w = wrow[ch];
                acc[0][ch] += xv[0] * w;
                acc[1][ch] += xv[1] * w;
                acc[2][ch] += xv[2] * w;
                acc[3][ch] += xv[3] * w;
            }
        }
    }

    #pragma unroll
    for (int off = 16; off > 0; off >>= 1)
        #pragma unroll
        for (int j = 0; j < 4; j++)
            #pragma unroll
            for (int ch = 0; ch < 18; ch++)
                acc[j][ch] += __shfl_down_sync(0xffffffffu, acc[j][ch], off);

    float* aw = ash + warp * 72;
    if (lane == 0) {
        #pragma unroll
        for (int j = 0; j < 4; j++)
            #pragma unroll
            for (int ch = 0; ch < 18; ch++)
                aw[j * 18 + ch] = acc[j][ch];
    }
    __syncwarp();

    for (int item = lane; item < 36; item += 32) {
        int j = item / 9;
        int p = item % 9;
        int ky = p / 3, kx = p % 3;
        float dy = aw[j * 18 + 2 * p]     + offset_b[2 * p];
        float dx = aw[j * 18 + 2 * p + 1] + offset_b[2 * p + 1];
        float py = dy + (float)ky + (float)(ho - 1);
        float px = dx + (float)kx + (float)(wo0 + j - 1);
        float y0f = floorf(py);
        float x0f = floorf(px);
        float wy = py - y0f;
        float wx = px - x0f;
        int y0 = (int)y0f;
        int x0 = (int)x0f;
        g_meta[((size_t)(n * PP + p)) * PIX_PER_N + ho * WO + wo0 + j] =
            make_float4(__int_as_float(y0), __int_as_float(x0), wy, wx);
    }
}

// ---------------- kernel 4: fused gather + GEMM (packed f32x2) + BN + SiLU ----------------
// block = one (n, ho) row: 64 pixels x 128 couts, K = 9*128.
// Thread tile 4 pixels x 8 couts, couts = {cr*4..+3} U {64+cr*4..+3} (conflict-free LDS.128).
// Inner product uses fma.rn.f32x2 (packed dual fp32 — ptxas never emits it from C++).
#define AS_STRIDE 132

__device__ __forceinline__ void fma2(ull& d, ull a, ull b) {
    asm("fma.rn.f32x2 %0, %1, %2, %0;" : "+l"(d) : "l"(a), "l"(b));
}
__device__ __forceinline__ ull bcast2(float a) {
    ull r; asm("mov.b64 %0, {%1, %1};" : "=l"(r) : "f"(a)); return r;
}

__global__ void k_main(const float* __restrict__ gamma,
                       const float* __restrict__ beta,
                       const float* __restrict__ rmean,
                       const float* __restrict__ rvar,
                       float* __restrict__ out) {
    extern __shared__ float sm[];
    float*  Bs  = sm;                                  // 16384 floats
    float*  As  = sm + 16384;                          // 64*132 = 8448 floats
    float4* msh = (float4*)(sm + 16384 + 8448);        // 576 float4
    float*  ssh = sm + 16384 + 8448 + 2304;            // 128
    float*  bsh = ssh + 128;                           // 128

    int tid = threadIdx.x;
    int ho  = blockIdx.x;
    int n   = blockIdx.y;

    for (int i = tid; i < PP * 64; i += 256) {
        int p  = i >> 6;
        int wo = i & 63;
        msh[i] = g_meta[((size_t)(n * PP + p)) * PIX_PER_N + ho * WO + wo];
    }
    if (tid < COUT) {
        float s = gamma[tid] * rsqrtf(rvar[tid] + 1e-5f);
        ssh[tid] = s;
        bsh[tid] = beta[tid] - rmean[tid] * s;
    }
    __syncthreads();

    int lane = tid & 31;
    int warp = tid >> 5;
    int pr   = tid >> 4;         // 0..15 pixel group
    int cr   = tid & 15;         // 0..15 cout group
    int pix0 = pr * 4;
    int c4   = cr * 4;           // first cout quartet base; second = 64 + c4

    // acc[j][q]: j = pixel, q = cout pair: q0,1 -> couts c4+{0,1},{2,3}; q2,3 -> 64+c4+{0,1},{2,3}
    ull acc[4][4];
    #pragma unroll
    for (int j = 0; j < 4; j++)
        #pragma unroll
        for (int q = 0; q < 4; q++) acc[j][q] = 0ull;

    const float* xn = g_xT + (size_t)n * HW * CIN;

    for (int p = 0; p < PP; p++) {
        // ---- gather As[pix][cin]: warp handles 8 pixels, lanes over cin ----
        int gpix0 = warp * 8;
        #pragma unroll
        for (int pl = 0; pl < 8; pl++) {
            int pix = gpix0 + pl;
            float4 m = msh[p * 64 + pix];
            int y0 = __float_as_int(m.x);
            int x0 = __float_as_int(m.y);
            float wy = m.z, wx = m.w;
            float w00 = (1.f - wy) * (1.f - wx);
            float w01 = (1.f - wy) * wx;
            float w10 = wy * (1.f - wx);
            float w11 = wy * wx;
            bool vy0 = (unsigned)y0       < (unsigned)HH;
            bool vy1 = (unsigned)(y0 + 1) < (unsigned)HH;
            bool vx0 = (unsigned)x0       < (unsigned)WW;
            bool vx1 = (unsigned)(x0 + 1) < (unsigned)WW;
            const float* r0 = xn + ((size_t)(y0 * WW)) * CIN;
            const float* r1 = r0 + (size_t)WW * CIN;
            #pragma unroll
            for (int cc = 0; cc < 4; cc++) {
                int c = cc * 32 + lane;
                float v = 0.f;
                if (vy0) {
                    if (vx0) v += w00 * r0[x0 * CIN + c];
                    if (vx1) v += w01 * r0[(x0 + 1) * CIN + c];
                }
                if (vy1) {
                    if (vx0) v += w10 * r1[x0 * CIN + c];
                    if (vx1) v += w11 * r1[(x0 + 1) * CIN + c];
                }
                As[pix * AS_STRIDE + c] = v;
            }
        }
        // ---- load Bs[k][cout] for this tap ----
        {
            const float4* src = (const float4*)(g_wT + (size_t)p * CIN * COUT);
            float4* dst = (float4*)Bs;
            #pragma unroll
            for (int i = tid; i < CIN * COUT / 4; i += 256)
                dst[i] = src[i];
        }
        __syncthreads();

        // ---- GEMM: 64x128 += As(64x128) * Bs(128x128), packed f32x2 ----
        #pragma unroll 8
        for (int k = 0; k < CIN; k++) {
            ull aa0 = bcast2(As[(pix0 + 0) * AS_STRIDE + k]);
            ull aa1 = bcast2(As[(pix0 + 1) * AS_STRIDE + k]);
            ull aa2 = bcast2(As[(pix0 + 2) * AS_STRIDE + k]);
            ull aa3 = bcast2(As[(pix0 + 3) * AS_STRIDE + k]);
            ulonglong2 b0 = *(const ulonglong2*)&Bs[k * COUT + c4];        // couts c4..c4+3
            ulonglong2 b1 = *(const ulonglong2*)&Bs[k * COUT + 64 + c4];   // couts 64+c4..+3
            fma2(acc[0][0], aa0, b0.x); fma2(acc[0][1], aa0, b0.y);
            fma2(acc[0][2], aa0, b1.x); fma2(acc[0][3], aa0, b1.y);
            fma2(acc[1][0], aa1, b0.x); fma2(acc[1][1], aa1, b0.y);
            fma2(acc[1][2], aa1, b1.x); fma2(acc[1][3], aa1, b1.y);
            fma2(acc[2][0], aa2, b0.x); fma2(acc[2][1], aa2, b0.y);
            fma2(acc[2][2], aa2, b1.x); fma2(acc[2][3], aa2, b1.y);
            fma2(acc[3][0], aa3, b0.x); fma2(acc[3][1], aa3, b0.y);
            fma2(acc[3][2], aa3, b1.x); fma2(acc[3][3], aa3, b1.y);
        }
        __syncthreads();
    }

    // ---- epilogue: BN + SiLU, vectorized store (4 consecutive wo) ----
    // unpack: acc[j][q] -> couts (base+2q') pairs
    #pragma unroll
    for (int q = 0; q < 4; q++) {
        int co_e = (q < 2 ? c4 : 64 + c4) + (q & 1) * 2;   // even cout of the pair
        float se = ssh[co_e],     be = bsh[co_e];
        float so = ssh[co_e + 1], bo = bsh[co_e + 1];
        float4 ve, vo;
        float lo, hi, y;
        #pragma unroll
        for (int j = 0; j < 4; j++) {
            asm("mov.b64 {%0, %1}, %2;" : "=f"(lo), "=f"(hi) : "l"(acc[j][q]));
            y = lo * se + be; ((float*)&ve)[j] = y / (1.f + expf(-y));
            y = hi * so + bo; ((float*)&vo)[j] = y / (1.f + expf(-y));
        }
        *(float4*)&out[(((size_t)(n * COUT + co_e))     * HO + ho) * WO + pix0] = ve;
        *(float4*)&out[(((size_t)(n * COUT + co_e + 1)) * HO + ho) * WO + pix0] = vo;
    }
}

// ---------------- launch ----------------
extern "C" void kernel_launch(void* const* d_in, const int* in_sizes, int n_in,
                              void* d_out, int out_size) {
    const float* x        = (const float*)d_in[0];
    const float* offset_w = (const float*)d_in[1];
    const float* offset_b = (const float*)d_in[2];
    const float* deform_w = (const float*)d_in[3];
    const float* gamma    = (const float*)d_in[4];
    const float* beta     = (const float*)d_in[5];
    const float* rmean    = (const float*)d_in[6];
    const float* rvar     = (const float*)d_in[7];
    float* out = (float*)d_out;

    static bool attr_done = false;
    if (!attr_done) {
        cudaFuncSetAttribute(k_offset_meta, cudaFuncAttributeMaxDynamicSharedMemorySize, 90000);
        cudaFuncSetAttribute(k_main,        cudaFuncAttributeMaxDynamicSharedMemorySize, 110592);
        attr_done = true;
    }

    k_transpose_x<<<dim3(HW / 32, CIN / 32, NB), dim3(32, 8)>>>(x);
    k_transpose_w<<<(PP * CIN * COUT + 255) / 256, 256>>>(deform_w);

    size_t sm3 = (size_t)(PP * CIN * 19 + 8 * 72) * sizeof(float);   // 89856 B
    k_offset_meta<<<NB * PIX_PER_N / 32, 256, sm3>>>(offset_w, offset_b);

    size_t sm4 = (size_t)(16384 + 8448 + 2304 + 256) * sizeof(float); // 109568 B
    k_main<<<dim3(HO, NB), 256, sm4>>>(gamma, beta, rmean, rvar, out);
}

// round 3
// speedup vs baseline: 2.1458x; 1.5256x over previous
#include <cuda_runtime.h>
#include <cuda_bf16.h>
#include <math.h>

typedef unsigned long long ull;

// Problem constants
#define NB   16
#define CIN  128
#define COUT 128
#define HH   64
#define WW   64
#define HO   64
#define WO   64
#define PP   9
#define HW   (HH*WW)
#define PIX_PER_N (HO*WO)

// ---------------- scratch ----------------
__device__ float  g_xT[NB * HH * WW * CIN];         // NHWC x
__device__ float4 g_meta[NB * PP * HO * WO];        // y0,x0(bitcast),wy,wx
__device__ float  g_wT[PP * CIN * COUT];            // [p][cin][cout]

// ---------------- packed f32x2 helpers ----------------
__device__ __forceinline__ void fma2(ull& d, ull a, ull b) {
    asm("fma.rn.f32x2 %0, %1, %2, %0;" : "+l"(d) : "l"(a), "l"(b));
}
__device__ __forceinline__ void add2(ull& d, ull a, ull b) {
    asm("add.rn.f32x2 %0, %1, %2;" : "=l"(d) : "l"(a), "l"(b));
}
__device__ __forceinline__ ull bcast2(float a) {
    ull r; asm("mov.b64 %0, {%1, %1};" : "=l"(r) : "f"(a)); return r;
}
__device__ __forceinline__ ull pack2(float lo, float hi) {
    ull r; asm("mov.b64 %0, {%1, %2};" : "=l"(r) : "f"(lo), "f"(hi)); return r;
}
__device__ __forceinline__ void unpack2(ull v, float& lo, float& hi) {
    asm("mov.b64 {%0, %1}, %2;" : "=f"(lo), "=f"(hi) : "l"(v));
}

// ---------------- kernel 1: x NCHW -> NHWC ----------------
__global__ void k_transpose_x(const float* __restrict__ x) {
    __shared__ float tile[32][33];
    int n   = blockIdx.z;
    int hw0 = blockIdx.x * 32;
    int c0  = blockIdx.y * 32;
    int tx = threadIdx.x, ty = threadIdx.y;
    #pragma unroll
    for (int i = 0; i < 32; i += 8)
        tile[ty + i][tx] = x[((size_t)(n * CIN + c0 + ty + i)) * HW + hw0 + tx];
    __syncthreads();
    #pragma unroll
    for (int i = 0; i < 32; i += 8)
        g_xT[((size_t)(n * HW + hw0 + ty + i)) * CIN + c0 + tx] = tile[tx][ty + i];
}

// ---------------- kernel 2: deform_w -> [p][cin][cout] ----------------
__global__ void k_transpose_w(const float* __restrict__ w) {
    int i = blockIdx.x * blockDim.x + threadIdx.x;
    if (i >= PP * CIN * COUT) return;
    int cout = i & 127;
    int cin  = (i >> 7) & 127;
    int p    = i >> 14;
    g_wT[i] = w[(cout * CIN + cin) * PP + p];
}

// ---------------- kernel 3: offset conv (f32x2) + bilinear metadata ----------------
// wsh2[p][q][cin] = pack(w[2q][cin][p], w[2q+1][cin][p]) — conflict-free LDS.64.
__global__ void k_offset_meta(const float* __restrict__ offset_w,
                              const float* __restrict__ offset_b) {
    extern __shared__ float sm_[];
    ull*   wsh2 = (ull*)sm_;                         // 9*9*128 = 10368 ull (82944 B)
    float* ash  = sm_ + 2 * 9 * 9 * CIN;             // 8 warps * 72 floats

    int tid = threadIdx.x;
    for (int i = tid; i < PP * 9 * CIN; i += blockDim.x) {
        int cin = i & 127;
        int q   = (i >> 7) % 9;
        int p   = i / (9 * CIN);
        float lo = offset_w[((2 * q)     * CIN + cin) * PP + p];
        float hi = offset_w[((2 * q + 1) * CIN + cin) * PP + p];
        wsh2[i] = pack2(lo, hi);
    }
    __syncthreads();

    int lane = tid & 31;
    int warp = tid >> 5;
    int gw   = blockIdx.x * 8 + warp;
    int pb   = gw * 4;
    int n    = pb >> 12;
    int r    = pb & 4095;
    int ho   = r >> 6;
    int wo0  = r & 63;

    ull acc2[4][9];
    #pragma unroll
    for (int j = 0; j < 4; j++)
        #pragma unroll
        for (int q = 0; q < 9; q++) acc2[j][q] = 0ull;

    const float* xn = g_xT + (size_t)n * HW * CIN;

    #pragma unroll
    for (int p = 0; p < PP; p++) {
        int ky = p / 3, kx = p % 3;
        int ih = ho + ky - 1;
        bool vrow = (unsigned)ih < (unsigned)HH;
        #pragma unroll
        for (int cc = 0; cc < 4; cc++) {
            int cin = cc * 32 + lane;
            ull xb[4];
            #pragma unroll
            for (int j = 0; j < 4; j++) {
                int iw = wo0 + j + kx - 1;
                bool v = vrow && ((unsigned)iw < (unsigned)WW);
                float xv = v ? xn[((size_t)(ih * WW + iw)) * CIN + cin] : 0.f;
                xb[j] = bcast2(xv);
            }
            const ull* wrow = wsh2 + p * (9 * CIN) + cin;
            #pragma unroll
            for (int q = 0; q < 9; q++) {
                ull wq = wrow[q * CIN];
                fma2(acc2[0][q], xb[0], wq);
                fma2(acc2[1][q], xb[1], wq);
                fma2(acc2[2][q], xb[2], wq);
                fma2(acc2[3][q], xb[3], wq);
            }
        }
    }

    #pragma unroll
    for (int off = 16; off > 0; off >>= 1)
        #pragma unroll
        for (int j = 0; j < 4; j++)
            #pragma unroll
            for (int q = 0; q < 9; q++) {
                ull o = __shfl_down_sync(0xffffffffu, acc2[j][q], off);
                add2(acc2[j][q], acc2[j][q], o);
            }

    float* aw = ash + warp * 72;
    if (lane == 0) {
        #pragma unroll
        for (int j = 0; j < 4; j++)
            #pragma unroll
            for (int q = 0; q < 9; q++) {
                float lo, hi;
                unpack2(acc2[j][q], lo, hi);
                aw[j * 18 + 2 * q]     = lo;
                aw[j * 18 + 2 * q + 1] = hi;
            }
    }
    __syncwarp();

    for (int item = lane; item < 36; item += 32) {
        int j = item / 9;
        int p = item % 9;
        int ky = p / 3, kx = p % 3;
        float dy = aw[j * 18 + 2 * p]     + offset_b[2 * p];
        float dx = aw[j * 18 + 2 * p + 1] + offset_b[2 * p + 1];
        float py = dy + (float)ky + (float)(ho - 1);
        float px = dx + (float)kx + (float)(wo0 + j - 1);
        float y0f = floorf(py);
        float x0f = floorf(px);
        g_meta[((size_t)(n * PP + p)) * PIX_PER_N + ho * WO + wo0 + j] =
            make_float4(__int_as_float((int)y0f), __int_as_float((int)x0f),
                        py - y0f, px - x0f);
    }
}

// ---------------- kernel 4: pipelined gather + f32x2 GEMM + BN + SiLU ----------------
// 512 threads, tile 128 px (2 ho rows) x 128 cout. As warp-private, double-buffered.
// Gather for tap p+1 interleaved (depth-2) inside GEMM of tap p.
#define AS_STR 132
#define AS_PER_BUF (8 * AS_STR)        // 1056 floats
#define AS_PER_WARP (2 * AS_PER_BUF)   // 2112

struct GBuf {
    float l00[4], l01[4], l10[4], l11[4];
    float w00, w01, w10, w11;
};

__device__ __forceinline__ void g_issue(GBuf& g, const float4* msh, int p1, int pix,
                                        const float* xn, int lane) {
    float4 m = msh[p1 * 128 + pix];
    int y0 = __float_as_int(m.x);
    int x0 = __float_as_int(m.y);
    float wy = m.z, wx = m.w;
    g.w00 = (1.f - wy) * (1.f - wx);
    g.w01 = (1.f - wy) * wx;
    g.w10 = wy * (1.f - wx);
    g.w11 = wy * wx;
    bool vy0 = (unsigned)y0       < (unsigned)HH;
    bool vy1 = (unsigned)(y0 + 1) < (unsigned)HH;
    bool vx0 = (unsigned)x0       < (unsigned)WW;
    bool vx1 = (unsigned)(x0 + 1) < (unsigned)WW;
    const float* r0 = xn + (long long)y0 * (WW * CIN);
    const float* r1 = r0 + WW * CIN;
    #pragma unroll
    for (int cc = 0; cc < 4; cc++) {
        int c = cc * 32 + lane;
        g.l00[cc] = (vy0 && vx0) ? r0[x0 * CIN + c]       : 0.f;
        g.l01[cc] = (vy0 && vx1) ? r0[(x0 + 1) * CIN + c] : 0.f;
        g.l10[cc] = (vy1 && vx0) ? r1[x0 * CIN + c]       : 0.f;
        g.l11[cc] = (vy1 && vx1) ? r1[(x0 + 1) * CIN + c] : 0.f;
    }
}
__device__ __forceinline__ void g_consume(GBuf& g, float* dst, int lane) {
    #pragma unroll
    for (int cc = 0; cc < 4; cc++) {
        float v = g.w00 * g.l00[cc] + g.w01 * g.l01[cc]
                + g.w10 * g.l10[cc] + g.w11 * g.l11[cc];
        dst[cc * 32 + lane] = v;
    }
}

__global__ __launch_bounds__(512, 1)
void k_main(const float* __restrict__ gamma,
            const float* __restrict__ beta,
            const float* __restrict__ rmean,
            const float* __restrict__ rvar,
            float* __restrict__ out) {
    extern __shared__ float sm[];
    float*  Bs  = sm;                         // 16384
    float*  As  = sm + 16384;                 // 16*2112 = 33792
    float4* msh = (float4*)(sm + 16384 + 33792);  // 9*128 float4 = 4608 floats
    float*  ssh = sm + 16384 + 33792 + 4608;  // 128
    float*  bsh = ssh + 128;                  // 128

    int tid  = threadIdx.x;
    int ho0  = blockIdx.x * 2;
    int n    = blockIdx.y;
    int lane = tid & 31;
    int warp = tid >> 5;
    int pr   = tid >> 4;       // 0..31
    int cr   = tid & 15;       // 0..15
    int c4   = cr * 4;
    int gpix0 = warp * 8;

    // stage metadata (128 pixels = 2 rows, 9 taps) + BN params
    for (int i = tid; i < PP * 128; i += 512) {
        int p   = i >> 7;
        int pix = i & 127;
        int row = ho0 + (pix >> 6);
        int wo  = pix & 63;
        msh[i] = g_meta[((size_t)(n * PP + p)) * PIX_PER_N + row * WO + wo];
    }
    if (tid < COUT) {
        float s = gamma[tid] * rsqrtf(rvar[tid] + 1e-5f);
        ssh[tid] = s;
        bsh[tid] = beta[tid] - rmean[tid] * s;
    }
    __syncthreads();

    const float* xn = g_xT + (size_t)n * HW * CIN;
    float* warpAs = As + warp * AS_PER_WARP;

    // prologue: gather tap 0 into buf 0; load Bs tap 0
    {
        GBuf g;
        #pragma unroll
        for (int pl = 0; pl < 8; pl++) {
            g_issue(g, msh, 0, gpix0 + pl, xn, lane);
            g_consume(g, warpAs + pl * AS_STR, lane);
        }
    }
    {
        const float4* src = (const float4*)g_wT;   // tap 0
        float4* dst = (float4*)Bs;
        #pragma unroll
        for (int i = tid; i < CIN * COUT / 4; i += 512) dst[i] = src[i];
    }
    __syncthreads();

    ull acc[4][4];
    #pragma unroll
    for (int j = 0; j < 4; j++)
        #pragma unroll
        for (int q = 0; q < 4; q++) acc[j][q] = 0ull;

    int buf = 0;
    for (int p = 0; p < PP; p++) {
        const float* asb   = warpAs + buf * AS_PER_BUF + (pr & 1) * (4 * AS_STR);
        float* nextAs      = warpAs + (buf ^ 1) * AS_PER_BUF;
        bool pref = (p < PP - 1);

        GBuf g0, g1;
        if (pref) {
            g_issue(g0, msh, p + 1, gpix0 + 0, xn, lane);
            g_issue(g1, msh, p + 1, gpix0 + 1, xn, lane);
        }

        #pragma unroll
        for (int ch = 0; ch < 8; ch++) {
            // ---- 16-k GEMM chunk ----
            #pragma unroll
            for (int k4 = 0; k4 < 16; k4 += 4) {
                int k = ch * 16 + k4;
                float4 a0 = *(const float4*)(asb + 0 * AS_STR + k);
                float4 a1 = *(const float4*)(asb + 1 * AS_STR + k);
                float4 a2 = *(const float4*)(asb + 2 * AS_STR + k);
                float4 a3 = *(const float4*)(asb + 3 * AS_STR + k);
                #pragma unroll
                for (int kk = 0; kk < 4; kk++) {
                    ulonglong2 b0 = *(const ulonglong2*)&Bs[(k + kk) * COUT + c4];
                    ulonglong2 b1 = *(const ulonglong2*)&Bs[(k + kk) * COUT + 64 + c4];
                    ull aa;
                    aa = bcast2(((const float*)&a0)[kk]);
                    fma2(acc[0][0], aa, b0.x); fma2(acc[0][1], aa, b0.y);
                    fma2(acc[0][2], aa, b1.x); fma2(acc[0][3], aa, b1.y);
                    aa = bcast2(((const float*)&a1)[kk]);
                    fma2(acc[1][0], aa, b0.x); fma2(acc[1][1], aa, b0.y);
                    fma2(acc[1][2], aa, b1.x); fma2(acc[1][3], aa, b1.y);
                    aa = bcast2(((const float*)&a2)[kk]);
                    fma2(acc[2][0], aa, b0.x); fma2(acc[2][1], aa, b0.y);
                    fma2(acc[2][2], aa, b1.x); fma2(acc[2][3], aa, b1.y);
                    aa = bcast2(((const float*)&a3)[kk]);
                    fma2(acc[3][0], aa, b0.x); fma2(acc[3][1], aa, b0.y);
                    fma2(acc[3][2], aa, b1.x); fma2(acc[3][3], aa, b1.y);
                }
            }
            // ---- consume gathered pixel ch, issue pixel ch+2 ----
            if (pref) {
                GBuf& gc = (ch & 1) ? g1 : g0;
                g_consume(gc, nextAs + ch * AS_STR, lane);
                if (ch < 6) g_issue(gc, msh, p + 1, gpix0 + ch + 2, xn, lane);
            }
        }

        __syncthreads();   // everyone done with Bs(p); As STS drained
        if (pref) {
            const float4* src = (const float4*)(g_wT + (size_t)(p + 1) * CIN * COUT);
            float4* dst = (float4*)Bs;
            #pragma unroll
            for (int i = tid; i < CIN * COUT / 4; i += 512) dst[i] = src[i];
        }
        __syncthreads();
        buf ^= 1;
    }

    // ---- epilogue: BN + SiLU ----
    int pix0 = pr * 4;
    int row  = ho0 + (pix0 >> 6);
    int wo0  = pix0 & 63;
    #pragma unroll
    for (int q = 0; q < 4; q++) {
        int co_e = (q < 2 ? c4 : 64 + c4) + (q & 1) * 2;
        float se = ssh[co_e],     be = bsh[co_e];
        float so = ssh[co_e + 1], bo = bsh[co_e + 1];
        float4 ve, vo;
        float lo, hi, y;
        #pragma unroll
        for (int j = 0; j < 4; j++) {
            unpack2(acc[j][q], lo, hi);
            y = lo * se + be; ((float*)&ve)[j] = y / (1.f + expf(-y));
            y = hi * so + bo; ((float*)&vo)[j] = y / (1.f + expf(-y));
        }
        *(float4*)&out[(((size_t)(n * COUT + co_e))     * HO + row) * WO + wo0] = ve;
        *(float4*)&out[(((size_t)(n * COUT + co_e + 1)) * HO + row) * WO + wo0] = vo;
    }
}

// ---------------- launch ----------------
extern "C" void kernel_launch(void* const* d_in, const int* in_sizes, int n_in,
                              void* d_out, int out_size) {
    const float* x        = (const float*)d_in[0];
    const float* offset_w = (const float*)d_in[1];
    const float* offset_b = (const float*)d_in[2];
    const float* deform_w = (const float*)d_in[3];
    const float* gamma    = (const float*)d_in[4];
    const float* beta     = (const float*)d_in[5];
    const float* rmean    = (const float*)d_in[6];
    const float* rvar     = (const float*)d_in[7];
    float* out = (float*)d_out;

    static bool attr_done = false;
    if (!attr_done) {
        cudaFuncSetAttribute(k_offset_meta, cudaFuncAttributeMaxDynamicSharedMemorySize, 90000);
        cudaFuncSetAttribute(k_main,        cudaFuncAttributeMaxDynamicSharedMemorySize, 221184);
        attr_done = true;
    }

    k_transpose_x<<<dim3(HW / 32, CIN / 32, NB), dim3(32, 8)>>>(x);
    k_transpose_w<<<(PP * CIN * COUT + 255) / 256, 256>>>(deform_w);

    size_t sm3 = (size_t)(PP * 9 * CIN) * 8 + (size_t)(8 * 72) * 4;  // 85248 B
    k_offset_meta<<<NB * PIX_PER_N / 32, 256, sm3>>>(offset_w, offset_b);

    size_t sm4 = (size_t)(16384 + 33792 + 4608 + 256) * sizeof(float); // 220160 B
    k_main<<<dim3(HO / 2, NB), 512, sm4>>>(gamma, beta, rmean, rvar, out);
}

// round 4
// speedup vs baseline: 3.2736x; 1.5256x over previous
#include <cuda_runtime.h>
#include <cuda_bf16.h>
#include <math.h>

typedef unsigned long long ull;
typedef unsigned int u32;

// Problem constants
#define NB   16
#define CIN  128
#define COUT 128
#define HH   64
#define WW   64
#define HO   64
#define WO   64
#define PP   9
#define HW   (HH*WW)
#define PIX_PER_N (HO*WO)

#define ROWB 272   // smem row stride in bytes (136 bf16 = 17*16B, conflict-free ldmatrix)

// ---------------- scratch ----------------
__device__ float  g_xT[NB * HH * WW * CIN];                    // NHWC x (fp32)
__device__ float4 g_meta[NB * PP * HO * WO];                   // y0,x0(bitcast),wy,wx
__device__ __align__(16) __nv_bfloat16 g_wh[PP * COUT * CIN];  // [p][cout][cin] hi
__device__ __align__(16) __nv_bfloat16 g_wl[PP * COUT * CIN];  // lo

// ---------------- packed f32x2 helpers (offset conv) ----------------
__device__ __forceinline__ void fma2(ull& d, ull a, ull b) {
    asm("fma.rn.f32x2 %0, %1, %2, %0;" : "+l"(d) : "l"(a), "l"(b));
}
__device__ __forceinline__ void add2(ull& d, ull a, ull b) {
    asm("add.rn.f32x2 %0, %1, %2;" : "=l"(d) : "l"(a), "l"(b));
}
__device__ __forceinline__ ull bcast2(float a) {
    ull r; asm("mov.b64 %0, {%1, %1};" : "=l"(r) : "f"(a)); return r;
}
__device__ __forceinline__ ull pack2(float lo, float hi) {
    ull r; asm("mov.b64 %0, {%1, %2};" : "=l"(r) : "f"(lo), "f"(hi)); return r;
}
__device__ __forceinline__ void unpack2(ull v, float& lo, float& hi) {
    asm("mov.b64 {%0, %1}, %2;" : "=f"(lo), "=f"(hi) : "l"(v));
}

// ---------------- mma helpers ----------------
__device__ __forceinline__ u32 cvta_smem(const void* p) {
    u32 r;
    asm("{ .reg .u64 t; cvta.to.shared.u64 t, %1; cvt.u32.u64 %0, t; }" : "=r"(r) : "l"(p));
    return r;
}
__device__ __forceinline__ void ldm4(u32* r, u32 addr) {
    asm volatile("ldmatrix.sync.aligned.m8n8.x4.shared.b16 {%0,%1,%2,%3}, [%4];"
                 : "=r"(r[0]), "=r"(r[1]), "=r"(r[2]), "=r"(r[3]) : "r"(addr));
}
__device__ __forceinline__ void mma_bf16(float* c, const u32* a, u32 b0, u32 b1) {
    asm volatile("mma.sync.aligned.m16n8k16.row.col.f32.bf16.bf16.f32 "
                 "{%0,%1,%2,%3}, {%4,%5,%6,%7}, {%8,%9}, {%0,%1,%2,%3};"
                 : "+f"(c[0]), "+f"(c[1]), "+f"(c[2]), "+f"(c[3])
                 : "r"(a[0]), "r"(a[1]), "r"(a[2]), "r"(a[3]), "r"(b0), "r"(b1));
}
__device__ __forceinline__ void cp_async16(u32 dst, const void* src) {
    asm volatile("cp.async.cg.shared.global [%0], [%1], 16;" :: "r"(dst), "l"(src));
}

// ---------------- kernel 1: x NCHW -> NHWC ----------------
__global__ void k_transpose_x(const float* __restrict__ x) {
    __shared__ float tile[32][33];
    int n   = blockIdx.z;
    int hw0 = blockIdx.x * 32;
    int c0  = blockIdx.y * 32;
    int tx = threadIdx.x, ty = threadIdx.y;
    #pragma unroll
    for (int i = 0; i < 32; i += 8)
        tile[ty + i][tx] = x[((size_t)(n * CIN + c0 + ty + i)) * HW + hw0 + tx];
    __syncthreads();
    #pragma unroll
    for (int i = 0; i < 32; i += 8)
        g_xT[((size_t)(n * HW + hw0 + ty + i)) * CIN + c0 + tx] = tile[tx][ty + i];
}

// ---------------- kernel 2: deform_w -> bf16 hi/lo [p][cout][cin] ----------------
__global__ void k_prep_w(const float* __restrict__ w) {
    int i = blockIdx.x * 256 + threadIdx.x;
    if (i >= PP * COUT * CIN) return;
    int cin  = i & 127;
    int cout = (i >> 7) & 127;
    int p    = i >> 14;
    float v = w[(cout * CIN + cin) * PP + p];
    __nv_bfloat16 h = __float2bfloat16_rn(v);
    g_wh[i] = h;
    g_wl[i] = __float2bfloat16_rn(v - __bfloat162float(h));
}

// ---------------- kernel 3: offset conv (f32x2) + bilinear metadata ----------------
__global__ void k_offset_meta(const float* __restrict__ offset_w,
                              const float* __restrict__ offset_b) {
    extern __shared__ float sm_[];
    ull*   wsh2 = (ull*)sm_;                         // 9*9*128 ull
    float* ash  = sm_ + 2 * 9 * 9 * CIN;             // 8 warps * 72 floats

    int tid = threadIdx.x;
    for (int i = tid; i < PP * 9 * CIN; i += blockDim.x) {
        int cin = i & 127;
        int q   = (i >> 7) % 9;
        int p   = i / (9 * CIN);
        float lo = offset_w[((2 * q)     * CIN + cin) * PP + p];
        float hi = offset_w[((2 * q + 1) * CIN + cin) * PP + p];
        wsh2[i] = pack2(lo, hi);
    }
    __syncthreads();

    int lane = tid & 31;
    int warp = tid >> 5;
    int gw   = blockIdx.x * 8 + warp;
    int pb   = gw * 4;
    int n    = pb >> 12;
    int r    = pb & 4095;
    int ho   = r >> 6;
    int wo0  = r & 63;

    ull acc2[4][9];
    #pragma unroll
    for (int j = 0; j < 4; j++)
        #pragma unroll
        for (int q = 0; q < 9; q++) acc2[j][q] = 0ull;

    const float* xn = g_xT + (size_t)n * HW * CIN;

    #pragma unroll
    for (int p = 0; p < PP; p++) {
        int ky = p / 3, kx = p % 3;
        int ih = ho + ky - 1;
        bool vrow = (unsigned)ih < (unsigned)HH;
        #pragma unroll
        for (int cc = 0; cc < 4; cc++) {
            int cin = cc * 32 + lane;
            ull xb[4];
            #pragma unroll
            for (int j = 0; j < 4; j++) {
                int iw = wo0 + j + kx - 1;
                bool v = vrow && ((unsigned)iw < (unsigned)WW);
                float xv = v ? xn[((size_t)(ih * WW + iw)) * CIN + cin] : 0.f;
                xb[j] = bcast2(xv);
            }
            const ull* wrow = wsh2 + p * (9 * CIN) + cin;
            #pragma unroll
            for (int q = 0; q < 9; q++) {
                ull wq = wrow[q * CIN];
                fma2(acc2[0][q], xb[0], wq);
                fma2(acc2[1][q], xb[1], wq);
                fma2(acc2[2][q], xb[2], wq);
                fma2(acc2[3][q], xb[3], wq);
            }
        }
    }

    #pragma unroll
    for (int off = 16; off > 0; off >>= 1)
        #pragma unroll
        for (int j = 0; j < 4; j++)
            #pragma unroll
            for (int q = 0; q < 9; q++) {
                ull o = __shfl_down_sync(0xffffffffu, acc2[j][q], off);
                add2(acc2[j][q], acc2[j][q], o);
            }

    float* aw = ash + warp * 72;
    if (lane == 0) {
        #pragma unroll
        for (int j = 0; j < 4; j++)
            #pragma unroll
            for (int q = 0; q < 9; q++) {
                float lo, hi;
                unpack2(acc2[j][q], lo, hi);
                aw[j * 18 + 2 * q]     = lo;
                aw[j * 18 + 2 * q + 1] = hi;
            }
    }
    __syncwarp();

    for (int item = lane; item < 36; item += 32) {
        int j = item / 9;
        int p = item % 9;
        int ky = p / 3, kx = p % 3;
        float dy = aw[j * 18 + 2 * p]     + offset_b[2 * p];
        float dx = aw[j * 18 + 2 * p + 1] + offset_b[2 * p + 1];
        float py = dy + (float)ky + (float)(ho - 1);
        float px = dx + (float)kx + (float)(wo0 + j - 1);
        float y0f = floorf(py);
        float x0f = floorf(px);
        g_meta[((size_t)(n * PP + p)) * PIX_PER_N + ho * WO + wo0 + j] =
            make_float4(__int_as_float((int)y0f), __int_as_float((int)x0f),
                        py - y0f, px - x0f);
    }
}

// ---------------- kernel 4: gather + bf16 split mma.sync GEMM + BN + SiLU ----------------
// 512 threads, tile 128px (2 ho rows) x 128co, 9 taps x 128ch.
// smem (bytes): BsH[0,34816) BsL[34816,69632) AsH[69632,104448) AsL[104448,139264)
//               msh[139264,157696) ssh[157696,+512) bsh[158208,+512)
#define OFF_BSH 0
#define OFF_BSL 34816
#define OFF_ASH 69632
#define OFF_ASL 104448
#define OFF_MSH 139264
#define OFF_SSH 157696
#define OFF_BBH 158208
#define SMEM_MAIN 158720

__device__ __forceinline__ void gather_tap(int p, int gpix0, int lane,
                                           const float4* msh, const float* xn,
                                           char* AsH, char* AsL) {
    #pragma unroll
    for (int pl = 0; pl < 8; pl++) {
        int pix = gpix0 + pl;
        float4 m = msh[p * 128 + pix];
        int y0 = __float_as_int(m.x);
        int x0 = __float_as_int(m.y);
        float wy = m.z, wx = m.w;
        float w00 = (1.f - wy) * (1.f - wx);
        float w01 = (1.f - wy) * wx;
        float w10 = wy * (1.f - wx);
        float w11 = wy * wx;
        bool vy0 = (unsigned)y0       < (unsigned)HH;
        bool vy1 = (unsigned)(y0 + 1) < (unsigned)HH;
        bool vx0 = (unsigned)x0       < (unsigned)WW;
        bool vx1 = (unsigned)(x0 + 1) < (unsigned)WW;
        const float* r0 = xn + (long long)y0 * (WW * CIN);
        const float* r1 = r0 + WW * CIN;
        #pragma unroll
        for (int cc = 0; cc < 2; cc++) {
            int ch0 = cc * 64 + lane * 2;
            float2 z = make_float2(0.f, 0.f);
            float2 v00 = (vy0 && vx0) ? *(const float2*)&r0[x0 * CIN + ch0]       : z;
            float2 v01 = (vy0 && vx1) ? *(const float2*)&r0[(x0 + 1) * CIN + ch0] : z;
            float2 v10 = (vy1 && vx0) ? *(const float2*)&r1[x0 * CIN + ch0]       : z;
            float2 v11 = (vy1 && vx1) ? *(const float2*)&r1[(x0 + 1) * CIN + ch0] : z;
            float v0 = w00 * v00.x + w01 * v01.x + w10 * v10.x + w11 * v11.x;
            float v1 = w00 * v00.y + w01 * v01.y + w10 * v10.y + w11 * v11.y;
            __nv_bfloat16 h0 = __float2bfloat16_rn(v0);
            __nv_bfloat16 h1 = __float2bfloat16_rn(v1);
            __nv_bfloat16 l0 = __float2bfloat16_rn(v0 - __bfloat162float(h0));
            __nv_bfloat16 l1 = __float2bfloat16_rn(v1 - __bfloat162float(h1));
            u32 uh = (u32)__bfloat16_as_ushort(h0) | ((u32)__bfloat16_as_ushort(h1) << 16);
            u32 ul = (u32)__bfloat16_as_ushort(l0) | ((u32)__bfloat16_as_ushort(l1) << 16);
            int off = pix * ROWB + cc * 128 + lane * 4;
            *(u32*)(AsH + off) = uh;
            *(u32*)(AsL + off) = ul;
        }
    }
}

__device__ __forceinline__ void load_bs_async(int p, int tid, u32 bsHu, u32 bsLu) {
    const char* srcH = (const char*)(g_wh + (size_t)p * COUT * CIN);
    const char* srcL = (const char*)(g_wl + (size_t)p * COUT * CIN);
    #pragma unroll
    for (int i = 0; i < 4; i++) {              // 2048 16B-chunks per matrix / 512 thr
        int c   = tid + i * 512;
        int row = c >> 4;
        int c16 = c & 15;
        u32 d = (u32)(row * ROWB + c16 * 16);
        cp_async16(bsHu + d, srcH + row * 256 + c16 * 16);
        cp_async16(bsLu + d, srcL + row * 256 + c16 * 16);
    }
    asm volatile("cp.async.commit_group;" ::: "memory");
}

__global__ __launch_bounds__(512, 1)
void k_main(const float* __restrict__ gamma,
            const float* __restrict__ beta,
            const float* __restrict__ rmean,
            const float* __restrict__ rvar,
            float* __restrict__ out) {
    extern __shared__ char smc[];
    char*   AsH = smc + OFF_ASH;
    char*   AsL = smc + OFF_ASL;
    float4* msh = (float4*)(smc + OFF_MSH);
    float*  ssh = (float*)(smc + OFF_SSH);
    float*  bsh = (float*)(smc + OFF_BBH);
    u32 sbase = cvta_smem(smc);
    u32 bsHu = sbase + OFF_BSH, bsLu = sbase + OFF_BSL;
    u32 asHu = sbase + OFF_ASH, asLu = sbase + OFF_ASL;

    int tid  = threadIdx.x;
    int ho0  = blockIdx.x * 2;
    int n    = blockIdx.y;
    int lane = tid & 31;
    int warp = tid >> 5;
    int wm   = warp >> 2;          // 0..3  (32-pixel group)
    int wn   = warp & 3;           // 0..3  (32-cout group)
    int gpix0 = warp * 8;          // gather ownership

    // stage metadata + BN params
    for (int i = tid; i < PP * 128; i += 512) {
        int p   = i >> 7;
        int pix = i & 127;
        int row = ho0 + (pix >> 6);
        int wo  = pix & 63;
        msh[i] = g_meta[((size_t)(n * PP + p)) * PIX_PER_N + row * WO + wo];
    }
    if (tid < COUT) {
        float s = gamma[tid] * rsqrtf(rvar[tid] + 1e-5f);
        ssh[tid] = s;
        bsh[tid] = beta[tid] - rmean[tid] * s;
    }
    __syncthreads();

    const float* xn = g_xT + (size_t)n * HW * CIN;

    // prologue: Bs(0) async + gather As(0)
    load_bs_async(0, tid, bsHu, bsLu);
    gather_tap(0, gpix0, lane, msh, xn, AsH, AsL);
    asm volatile("cp.async.wait_group 0;" ::: "memory");
    __syncthreads();

    float acc[2][4][4];
    #pragma unroll
    for (int mt = 0; mt < 2; mt++)
        #pragma unroll
        for (int nt = 0; nt < 4; nt++)
            #pragma unroll
            for (int i = 0; i < 4; i++) acc[mt][nt][i] = 0.f;

    int lrow = lane & 15;
    int lcol = (lane >> 4) << 4;

    for (int p = 0; p < PP; p++) {
        // ---- GEMM over 8 k-steps of 16 ----
        #pragma unroll
        for (int ks = 0; ks < 8; ks++) {
            int k0b = ks * 32 + lcol;     // byte offset in row (16 bf16 = 32B per step)
            u32 ah[2][4], al[2][4], bh[2][4], bl[2][4];
            #pragma unroll
            for (int mt = 0; mt < 2; mt++) {
                u32 ra = (u32)((wm * 32 + mt * 16 + lrow) * ROWB + k0b);
                ldm4(ah[mt], asHu + ra);
                ldm4(al[mt], asLu + ra);
            }
            #pragma unroll
            for (int pr = 0; pr < 2; pr++) {
                u32 rb = (u32)((wn * 32 + pr * 16 + lrow) * ROWB + k0b);
                ldm4(bh[pr], bsHu + rb);
                ldm4(bl[pr], bsLu + rb);
            }
            #pragma unroll
            for (int mt = 0; mt < 2; mt++)
                #pragma unroll
                for (int nt = 0; nt < 4; nt++) {
                    int pr = nt >> 1, s = nt & 1;
                    u32 b0h = bh[pr][s], b1h = bh[pr][2 + s];
                    u32 b0l = bl[pr][s], b1l = bl[pr][2 + s];
                    mma_bf16(acc[mt][nt], ah[mt], b0h, b1h);
                    mma_bf16(acc[mt][nt], ah[mt], b0l, b1l);
                    mma_bf16(acc[mt][nt], al[mt], b0h, b1h);
                }
        }
        __syncthreads();                  // done reading As/Bs for tap p
        if (p < PP - 1) {
            load_bs_async(p + 1, tid, bsHu, bsLu);
            gather_tap(p + 1, gpix0, lane, msh, xn, AsH, AsL);
            asm volatile("cp.async.wait_group 0;" ::: "memory");
            __syncthreads();
        }
    }

    // ---- epilogue: BN + SiLU ----
    #pragma unroll
    for (int mt = 0; mt < 2; mt++)
        #pragma unroll
        for (int nt = 0; nt < 4; nt++) {
            int co = wn * 32 + nt * 8 + (lane & 3) * 2;
            int px = wm * 32 + mt * 16 + (lane >> 2);
            float s0 = ssh[co],     b0 = bsh[co];
            float s1 = ssh[co + 1], b1 = bsh[co + 1];
            #pragma unroll
            for (int h = 0; h < 2; h++) {
                int pr_ = px + h * 8;
                int row = ho0 + (pr_ >> 6);
                int wo  = pr_ & 63;
                float y0v = acc[mt][nt][h * 2 + 0] * s0 + b0;
                float y1v = acc[mt][nt][h * 2 + 1] * s1 + b1;
                out[(((size_t)(n * COUT + co))     * HO + row) * WO + wo] = y0v / (1.f + expf(-y0v));
                out[(((size_t)(n * COUT + co + 1)) * HO + row) * WO + wo] = y1v / (1.f + expf(-y1v));
            }
        }
}

// ---------------- launch ----------------
extern "C" void kernel_launch(void* const* d_in, const int* in_sizes, int n_in,
                              void* d_out, int out_size) {
    const float* x        = (const float*)d_in[0];
    const float* offset_w = (const float*)d_in[1];
    const float* offset_b = (const float*)d_in[2];
    const float* deform_w = (const float*)d_in[3];
    const float* gamma    = (const float*)d_in[4];
    const float* beta     = (const float*)d_in[5];
    const float* rmean    = (const float*)d_in[6];
    const float* rvar     = (const float*)d_in[7];
    float* out = (float*)d_out;

    cudaFuncSetAttribute(k_offset_meta, cudaFuncAttributeMaxDynamicSharedMemorySize, 90000);
    cudaFuncSetAttribute(k_main,        cudaFuncAttributeMaxDynamicSharedMemorySize, SMEM_MAIN);

    k_transpose_x<<<dim3(HW / 32, CIN / 32, NB), dim3(32, 8)>>>(x);
    k_prep_w<<<(PP * COUT * CIN + 255) / 256, 256>>>(deform_w);

    size_t sm3 = (size_t)(PP * 9 * CIN) * 8 + (size_t)(8 * 72) * 4;  // 85248 B
    k_offset_meta<<<NB * PIX_PER_N / 32, 256, sm3>>>(offset_w, offset_b);

    k_main<<<dim3(HO / 2, NB), 512, SMEM_MAIN>>>(gamma, beta, rmean, rvar, out);
}